// round 1
// baseline (speedup 1.0000x reference)
#include <cuda_runtime.h>
#include <math.h>

// Problem constants (fixed shapes)
#define BB 2
#define TT 2048
#define CC 1024
#define HH 16
#define HD 64
#define RR 8
#define DSTD 56

// Scratch (static device globals — no allocation)
__device__ float g_qkv[(size_t)BB * TT * 3 * CC];   // (B,T,3C)   48 MB
__device__ float g_qa[(size_t)BB * HH * TT * HD];   // (B,H,T,64) 16 MB
__device__ float g_ka[(size_t)BB * HH * TT * HD];   // (B,H,T,64) 16 MB
__device__ float g_ao[(size_t)BB * TT * CC];        // (B,T,C)    16 MB

// ---------------------------------------------------------------------------
// GEMM (NT): C[m,n] = sum_k A[m,k] * B[n,k]
// A: (M,K) row-major, B: (N,K) row-major. M,N % 64 == 0, K % 32 == 0.
// 64x64 tile, BK=32, 256 threads, 4x4 micro-tile per thread.
// ---------------------------------------------------------------------------
__global__ __launch_bounds__(256) void gemm_nt(
    const float* __restrict__ A, const float* __restrict__ B,
    float* __restrict__ C, int M, int N, int K)
{
    __shared__ float As[32][68];  // [k][m], padded for conflict-free float4
    __shared__ float Bs[32][68];  // [k][n]

    const int bm = blockIdx.y * 64;
    const int bn = blockIdx.x * 64;
    const int tid = threadIdx.x;
    const int tx = tid & 15;
    const int ty = tid >> 4;

    float acc[4][4];
#pragma unroll
    for (int i = 0; i < 4; i++)
#pragma unroll
        for (int j = 0; j < 4; j++) acc[i][j] = 0.f;

    for (int k0 = 0; k0 < K; k0 += 32) {
#pragma unroll
        for (int it = 0; it < 2; it++) {
            int idx = tid + it * 256;          // 0..511
            int row = idx >> 3;                // 0..63
            int c4  = idx & 7;                 // 0..7 (float4 col)
            float4 va = *(const float4*)(A + (size_t)(bm + row) * K + k0 + c4 * 4);
            As[c4 * 4 + 0][row] = va.x;
            As[c4 * 4 + 1][row] = va.y;
            As[c4 * 4 + 2][row] = va.z;
            As[c4 * 4 + 3][row] = va.w;
            float4 vb = *(const float4*)(B + (size_t)(bn + row) * K + k0 + c4 * 4);
            Bs[c4 * 4 + 0][row] = vb.x;
            Bs[c4 * 4 + 1][row] = vb.y;
            Bs[c4 * 4 + 2][row] = vb.z;
            Bs[c4 * 4 + 3][row] = vb.w;
        }
        __syncthreads();

#pragma unroll
        for (int k = 0; k < 32; k++) {
            float4 ra = *(const float4*)&As[k][ty * 4];
            float4 rb = *(const float4*)&Bs[k][tx * 4];
            float a_[4] = {ra.x, ra.y, ra.z, ra.w};
            float b_[4] = {rb.x, rb.y, rb.z, rb.w};
#pragma unroll
            for (int i = 0; i < 4; i++)
#pragma unroll
                for (int j = 0; j < 4; j++) acc[i][j] += a_[i] * b_[j];
        }
        __syncthreads();
    }

#pragma unroll
    for (int i = 0; i < 4; i++) {
        float4 v = make_float4(acc[i][0], acc[i][1], acc[i][2], acc[i][3]);
        *(float4*)(C + (size_t)(bm + ty * 4 + i) * N + bn + tx * 4) = v;
    }
}

// ---------------------------------------------------------------------------
// Augmentation: for each (b,h,t) build
//   qa = [sqrt(w_std)*q[:56], sqrt(w_rec)*k_low]   (cross: q carries k_low)
//   ka = [sqrt(w_std)*k[:56], sqrt(w_rec)*q_low]
// One block per (b,h,t), 64 threads (one per dim).
// ---------------------------------------------------------------------------
__global__ __launch_bounds__(64) void augment_kernel(
    const float* __restrict__ qkv, float* __restrict__ qa, float* __restrict__ ka,
    const float* __restrict__ W_recip, const float* __restrict__ w_std,
    const float* __restrict__ w_rec)
{
    const int idx = blockIdx.x;            // (b*H + h)*T + t
    const int t = idx % TT;
    const int h = (idx / TT) % HH;
    const int b = idx / (TT * HH);

    const float* base = qkv + (size_t)(b * TT + t) * (3 * CC);
    const int d = threadIdx.x;             // 0..63

    float qd = base[h * HD + d];
    float kd = base[CC + h * HD + d];

    __shared__ float sq[HD], sk[HD], qlow[RR], klow[RR];
    sq[d] = qd;
    sk[d] = kd;
    __syncthreads();

    if (d < RR) {
        float s = 0.f;
#pragma unroll
        for (int i = 0; i < HD; i++) s += sq[i] * W_recip[i * RR + d];
        qlow[d] = s;
    } else if (d < 2 * RR) {
        int r = d - RR;
        float s = 0.f;
#pragma unroll
        for (int i = 0; i < HD; i++) s += sk[i] * W_recip[i * RR + r];
        klow[r] = s;
    }
    __syncthreads();

    const float sws = sqrtf(w_std[h]);
    const float swr = sqrtf(w_rec[h]);
    float qav = (d < DSTD) ? sws * qd : swr * klow[d - DSTD];
    float kav = (d < DSTD) ? sws * kd : swr * qlow[d - DSTD];

    size_t o = ((size_t)idx) * HD + d;
    qa[o] = qav;
    ka[o] = kav;
}

// ---------------------------------------------------------------------------
// Flash attention (causal) with per-head key bias.
// Grid: (T/128, B*H). 128 threads, one query row per thread.
// Key tiles of 64 (ka + v staged in smem). Output written in (B,T,H,64).
// ---------------------------------------------------------------------------
#define QB 128
#define KT 64

__global__ __launch_bounds__(128) void flash_kernel(
    const float* __restrict__ qa, const float* __restrict__ ka,
    const float* __restrict__ qkv, const float* __restrict__ d_bias,
    const float* __restrict__ w_disc, float* __restrict__ ao)
{
    const int bh = blockIdx.y;
    const int b = bh / HH;
    const int h = bh % HH;
    const int t0 = blockIdx.x * QB;
    const int tid = threadIdx.x;           // 0..127
    const int t = t0 + tid;                // this thread's query row

    __shared__ float skk[KT][HD];
    __shared__ float svv[KT][HD];
    __shared__ float sb[KT];

    // Load q_aug row into registers
    const float* qrow = qa + ((size_t)bh * TT + t) * HD;
    float qreg[HD];
#pragma unroll
    for (int d = 0; d < HD; d++) qreg[d] = qrow[d];

    float m = -1e30f, l = 0.f;
    float acc[HD];
#pragma unroll
    for (int d = 0; d < HD; d++) acc[d] = 0.f;

    const float wd = w_disc[h];
    const int nk = t0 + QB;                // keys in [0, nk)

    for (int s0 = 0; s0 < nk; s0 += KT) {
        __syncthreads();
        // Stage ka tile and v tile (64 rows x 64 floats each)
        const float* kbase = ka + ((size_t)bh * TT + s0) * HD;
#pragma unroll
        for (int it = 0; it < 8; it++) {
            int i = tid + it * 128;        // 0..1023 float4 slots
            int row = i >> 4;
            int c4 = i & 15;
            ((float4*)&skk[row][0])[c4] = ((const float4*)(kbase + row * HD))[c4];
            const float* vrow = qkv + (size_t)(b * TT + s0 + row) * (3 * CC) + 2 * CC + h * HD;
            ((float4*)&svv[row][0])[c4] = ((const float4*)vrow)[c4];
        }
        if (tid < KT) sb[tid] = wd * d_bias[h * TT + s0 + tid];
        __syncthreads();

        int jmax = t - s0 + 1;             // causal: keys s0+j <= t
        if (jmax > KT) jmax = KT;
        for (int j = 0; j < jmax; j++) {
            float s = 0.f;
#pragma unroll
            for (int d = 0; d < HD; d++) s += qreg[d] * skk[j][d];
            s = s * 0.125f + sb[j];

            if (s <= m) {
                float p = __expf(s - m);
                l += p;
#pragma unroll
                for (int d = 0; d < HD; d++) acc[d] += p * svv[j][d];
            } else {
                float corr = __expf(m - s);  // p = 1 at the new max
                l = l * corr + 1.f;
#pragma unroll
                for (int d = 0; d < HD; d++) acc[d] = acc[d] * corr + svv[j][d];
                m = s;
            }
        }
    }

    const float inv = 1.f / l;
    float* orow = ao + ((size_t)(b * TT + t) * HH + h) * HD;
#pragma unroll
    for (int d = 0; d < HD; d++) orow[d] = acc[d] * inv;
}

// ---------------------------------------------------------------------------
// Launch
// ---------------------------------------------------------------------------
extern "C" void kernel_launch(void* const* d_in, const int* in_sizes, int n_in,
                              void* d_out, int out_size)
{
    const float* x       = (const float*)d_in[0];
    const float* Wqkv    = (const float*)d_in[1];
    const float* Wproj   = (const float*)d_in[2];
    const float* W_recip = (const float*)d_in[3];
    const float* w_std   = (const float*)d_in[4];
    const float* w_rec   = (const float*)d_in[5];
    const float* w_disc  = (const float*)d_in[6];
    const float* d_bias  = (const float*)d_in[7];
    float* out = (float*)d_out;

    float *p_qkv, *p_qa, *p_ka, *p_ao;
    cudaGetSymbolAddress((void**)&p_qkv, g_qkv);
    cudaGetSymbolAddress((void**)&p_qa, g_qa);
    cudaGetSymbolAddress((void**)&p_ka, g_ka);
    cudaGetSymbolAddress((void**)&p_ao, g_ao);

    const int M = BB * TT;   // 4096

    // 1) qkv = x @ Wqkv^T   (4096 x 3072, K=1024)
    gemm_nt<<<dim3((3 * CC) / 64, M / 64), 256>>>(x, Wqkv, p_qkv, M, 3 * CC, CC);

    // 2) cross augmentation
    augment_kernel<<<BB * HH * TT, 64>>>(p_qkv, p_qa, p_ka, W_recip, w_std, w_rec);

    // 3) causal flash attention with key bias
    flash_kernel<<<dim3(TT / QB, BB * HH), 128>>>(p_qa, p_ka, p_qkv, d_bias, w_disc, p_ao);

    // 4) out = ao @ Wproj^T  (4096 x 1024, K=1024)
    gemm_nt<<<dim3(CC / 64, M / 64), 256>>>(p_ao, Wproj, out, M, CC, CC);
}